// round 10
// baseline (speedup 1.0000x reference)
#include <cuda_runtime.h>
#include <cstdint>

#define NPTS 500000
#define NSEG 80000
#define SEGW 92
#define DIN 182
#define NT_B 3907
#define NT_A 625
#define GRID 296
#define KP 92                 // padded K for both GEMM passes (91 + 1)

__device__ __align__(16) float g_seg[NSEG * SEGW];
__device__ __align__(16) float g_Y[(size_t)NSEG * 128];
__device__ float g_sum[128], g_sumsq[128], g_scale[128], g_shift[128];
__device__ int g_flags;

// ---- f32x2 packed helpers ----
__device__ __forceinline__ unsigned long long pk2(float a) {
    unsigned long long r; asm("mov.b64 %0,{%1,%1};" : "=l"(r) : "f"(a)); return r;
}
__device__ __forceinline__ void upk(unsigned long long v, float& a, float& b) {
    asm("mov.b64 {%0,%1},%2;" : "=f"(a), "=f"(b) : "l"(v));
}
__device__ __forceinline__ void fma2(unsigned long long& d, unsigned long long a, unsigned long long b) {
    asm("fma.rn.f32x2 %0,%1,%2,%0;" : "+l"(d) : "l"(a), "l"(b));
}
__device__ __forceinline__ int fg_of(const void* m, int p, int fl) {
    if (fl & 2) return ((const float*)m)[p] != 0.0f;
    if (fl & 1) return ((const unsigned char*)m)[p] != 0;
    return ((const int*)m)[p] != 0;
}

// ---------------- K0: zero scratch ----------------
__global__ __launch_bounds__(256) void k_zero() {
    int64_t i = (int64_t)blockIdx.x * blockDim.x + threadIdx.x;
    int64_t st = (int64_t)gridDim.x * blockDim.x;
    float4 z = make_float4(0.f, 0.f, 0.f, 0.f);
    for (int64_t j = i; j < (int64_t)NSEG * SEGW / 4; j += st) ((float4*)g_seg)[j] = z;
    if (i < 128) { g_sum[i] = 0.f; g_sumsq[i] = 0.f; }
    if (i == 0) g_flags = 0;
}

// ---------------- K1: detect fg_mask dtype ----------------
__global__ __launch_bounds__(256) void k_detect(const unsigned int* __restrict__ w) {
    int f = 0;
    for (int i = blockIdx.x * blockDim.x + threadIdx.x; i < 125000; i += gridDim.x * blockDim.x) {
        unsigned int x = w[i];
        if (x == 0x3f800000u) f |= 2;
        else if (x > 1u) f |= 1;
    }
    if (f) atomicOr(&g_flags, f);
}

// ---------------- K2: scatter segment sums ----------------
__global__ __launch_bounds__(256) void k_scatter(
    const float* __restrict__ pts, const float* __restrict__ proj,
    const float* __restrict__ feat, const float* __restrict__ logi,
    const int* __restrict__ cidx, const void* __restrict__ fgm) {
    const int fl = g_flags;
    const int lane = threadIdx.x & 31;
    const int gw = (blockIdx.x * blockDim.x + threadIdx.x) >> 5;
    const int nw = (gridDim.x * blockDim.x) >> 5;
    for (int p = gw; p < NPTS; p += nw) {
        int ci = 0, g = 0;
        if (lane == 0) { ci = cidx[p]; g = fg_of(fgm, p, fl); }
        ci = __shfl_sync(0xffffffffu, ci, 0);
        g  = __shfl_sync(0xffffffffu, g, 0);
        float* row = g_seg + (size_t)(ci * 2 + g) * SEGW;
        if (lane < 23) {
            float4 v;
            if (lane < 16)       v = *(const float4*)(feat + (size_t)p * 64 + lane * 4);
            else if (lane < 21)  v = *(const float4*)(logi + (size_t)p * 20 + (lane - 16) * 4);
            else if (lane == 21) v = *(const float4*)(pts + (size_t)p * 4);
            else {
                const float* pr = proj + (size_t)p * 3;
                v = make_float4(pr[0], pr[1], pr[2], 1.0f);
            }
            asm volatile("red.global.add.v4.f32 [%0],{%1,%2,%3,%4};"
                         :: "l"(row + lane * 4), "f"(v.x), "f"(v.y), "f"(v.z), "f"(v.w) : "memory");
        }
    }
}

// ======== FFMA2 inner block: 16m x 4n per thread, K=KP ========
#define MMA_BODY(ws, xs, acc, tx, ty)                                        \
    _Pragma("unroll 4")                                                       \
    for (int k = 0; k < KP; k++) {                                            \
        const float* xr = (xs) + k * 128 + (ty) * 16;                         \
        ulonglong2 a0 = *(const ulonglong2*)xr;                               \
        ulonglong2 a1 = *(const ulonglong2*)(xr + 4);                         \
        ulonglong2 a2 = *(const ulonglong2*)(xr + 8);                         \
        ulonglong2 a3 = *(const ulonglong2*)(xr + 12);                        \
        float4 b = *(const float4*)((ws) + k * 128 + (tx) * 4);               \
        unsigned long long b0 = pk2(b.x), b1 = pk2(b.y),                      \
                           b2 = pk2(b.z), b3 = pk2(b.w);                      \
        fma2(acc[0], a0.x, b0);  fma2(acc[1], a0.y, b0);                      \
        fma2(acc[2], a1.x, b0);  fma2(acc[3], a1.y, b0);                      \
        fma2(acc[4], a2.x, b0);  fma2(acc[5], a2.y, b0);                      \
        fma2(acc[6], a3.x, b0);  fma2(acc[7], a3.y, b0);                      \
        fma2(acc[8], a0.x, b1);  fma2(acc[9], a0.y, b1);                      \
        fma2(acc[10], a1.x, b1); fma2(acc[11], a1.y, b1);                     \
        fma2(acc[12], a2.x, b1); fma2(acc[13], a2.y, b1);                     \
        fma2(acc[14], a3.x, b1); fma2(acc[15], a3.y, b1);                     \
        fma2(acc[16], a0.x, b2); fma2(acc[17], a0.y, b2);                     \
        fma2(acc[18], a1.x, b2); fma2(acc[19], a1.y, b2);                     \
        fma2(acc[20], a2.x, b2); fma2(acc[21], a2.y, b2);                     \
        fma2(acc[22], a3.x, b2); fma2(acc[23], a3.y, b2);                     \
        fma2(acc[24], a0.x, b3); fma2(acc[25], a0.y, b3);                     \
        fma2(acc[26], a1.x, b3); fma2(acc[27], a1.y, b3);                     \
        fma2(acc[28], a2.x, b3); fma2(acc[29], a2.y, b3);                     \
        fma2(acc[30], a3.x, b3); fma2(acc[31], a3.y, b3);                     \
    }

// own-point gather into xs[k][m], K=92 layout
__device__ __forceinline__ void gather_own(
    float* xc, const float* pts, const float* proj, const float* feat,
    const float* logi, int p, bool ok, int half) {
    if (half == 0) {
        if (ok) {
            #pragma unroll
            for (int q = 0; q < 12; q++) {
                float4 f = *(const float4*)(feat + (size_t)p * 64 + 4 * q);
                xc[(4 * q + 0) * 128] = f.x; xc[(4 * q + 1) * 128] = f.y;
                xc[(4 * q + 2) * 128] = f.z; xc[(4 * q + 3) * 128] = f.w;
            }
        } else {
            #pragma unroll
            for (int k = 0; k < 48; k++) xc[k * 128] = 0.f;
        }
    } else {
        if (ok) {
            #pragma unroll
            for (int q = 0; q < 4; q++) {
                float4 f = *(const float4*)(feat + (size_t)p * 64 + 48 + 4 * q);
                xc[(48 + 4 * q) * 128] = f.x; xc[(49 + 4 * q) * 128] = f.y;
                xc[(50 + 4 * q) * 128] = f.z; xc[(51 + 4 * q) * 128] = f.w;
            }
            #pragma unroll
            for (int q = 0; q < 5; q++) {
                float4 f = *(const float4*)(logi + (size_t)p * 20 + 4 * q);
                xc[(64 + 4 * q) * 128] = f.x; xc[(65 + 4 * q) * 128] = f.y;
                xc[(66 + 4 * q) * 128] = f.z; xc[(67 + 4 * q) * 128] = f.w;
            }
            float4 f = *(const float4*)(pts + (size_t)p * 4);
            xc[84 * 128] = f.x; xc[85 * 128] = f.y; xc[86 * 128] = f.z; xc[87 * 128] = f.w;
            const float* pr = proj + (size_t)p * 3;
            xc[88 * 128] = pr[0]; xc[89 * 128] = pr[1]; xc[90 * 128] = pr[2];
        } else {
            #pragma unroll
            for (int k = 48; k < 91; k++) xc[k * 128] = 0.f;
        }
        xc[91 * 128] = 0.f;
    }
}

// ---------------- K3: pass A — Y[s] = W2*mean[s] + bias ----------------
#define SMEM_A ((KP * 128 * 2 + 128) * 4)
__global__ __launch_bounds__(256, 2) void k_segmm(const float* __restrict__ W,
                                                  const float* __restrict__ bias) {
    extern __shared__ __align__(16) float smf[];
    float* ws = smf;
    float* xs = smf + KP * 128;
    float* bias_s = smf + KP * 256;

    const int tid = threadIdx.x;
    const int tx = tid & 31, ty = tid >> 5;
    const int r = tid & 127, half = tid >> 7;

    for (int i = tid; i < KP * 128; i += 256) {
        int k = i >> 7, n = i & 127;
        ws[i] = (k < 91) ? W[n * DIN + 91 + k] : 0.f;
    }
    if (tid < 128) bias_s[tid] = bias[tid];
    __syncthreads();

    for (int t = blockIdx.x; t < NT_A; t += GRID) {
        const int s = t * 128 + r;
        const float* row = g_seg + (size_t)s * SEGW;
        float cnt = row[91];
        float inv = (cnt > 0.f) ? (1.0f / cnt) : 0.f;
        float* xc = xs + r;
        if (half == 0) {
            #pragma unroll
            for (int q = 0; q < 12; q++) {
                float4 f = *(const float4*)(row + 4 * q);
                xc[(4 * q + 0) * 128] = f.x * inv; xc[(4 * q + 1) * 128] = f.y * inv;
                xc[(4 * q + 2) * 128] = f.z * inv; xc[(4 * q + 3) * 128] = f.w * inv;
            }
        } else {
            #pragma unroll
            for (int q = 0; q < 10; q++) {
                float4 f = *(const float4*)(row + 48 + 4 * q);
                xc[(48 + 4 * q) * 128] = f.x * inv; xc[(49 + 4 * q) * 128] = f.y * inv;
                xc[(50 + 4 * q) * 128] = f.z * inv; xc[(51 + 4 * q) * 128] = f.w * inv;
            }
            xc[88 * 128] = row[88] * inv;
            xc[89 * 128] = row[89] * inv;
            xc[90 * 128] = row[90] * inv;
            xc[91 * 128] = 0.f;
        }
        __syncthreads();

        unsigned long long acc[32];
        #pragma unroll
        for (int i = 0; i < 32; i++) acc[i] = 0ull;
        MMA_BODY(ws, xs, acc, tx, ty)

        const float bj0 = bias_s[tx * 4], bj1 = bias_s[tx * 4 + 1];
        const float bj2 = bias_s[tx * 4 + 2], bj3 = bias_s[tx * 4 + 3];
        #pragma unroll
        for (int pr = 0; pr < 8; pr++) {
            int s0 = t * 128 + ty * 16 + 2 * pr;
            float c0[4], c1[4];
            upk(acc[pr],      c0[0], c1[0]);
            upk(acc[8 + pr],  c0[1], c1[1]);
            upk(acc[16 + pr], c0[2], c1[2]);
            upk(acc[24 + pr], c0[3], c1[3]);
            *(float4*)(g_Y + (size_t)s0 * 128 + tx * 4) =
                make_float4(c0[0] + bj0, c0[1] + bj1, c0[2] + bj2, c0[3] + bj3);
            *(float4*)(g_Y + (size_t)(s0 + 1) * 128 + tx * 4) =
                make_float4(c1[0] + bj0, c1[1] + bj1, c1[2] + bj2, c1[3] + bj3);
        }
        __syncthreads();
    }
}

// ---------------- K4a (fork): pure W1 GEMM, h = W1*own ----------------
#define SMEM_W1 ((KP * 128 * 2) * 4)
__global__ __launch_bounds__(256, 2) void k_ptmm_w1(
    const float* __restrict__ pts, const float* __restrict__ proj,
    const float* __restrict__ feat, const float* __restrict__ logi,
    const float* __restrict__ W, float* __restrict__ hout)
{
    extern __shared__ __align__(16) float smf[];
    float* ws = smf;
    float* xs = smf + KP * 128;

    const int tid = threadIdx.x;
    const int tx = tid & 31, ty = tid >> 5;
    const int r = tid & 127, half = tid >> 7;

    for (int i = tid; i < KP * 128; i += 256) {
        int k = i >> 7, n = i & 127;
        ws[i] = (k < 91) ? W[n * DIN + k] : 0.f;
    }
    __syncthreads();

    for (int t = blockIdx.x; t < NT_B; t += GRID) {
        const int p = t * 128 + r;
        gather_own(xs + r, pts, proj, feat, logi, p, p < NPTS, half);
        __syncthreads();

        unsigned long long acc[32];
        #pragma unroll
        for (int i = 0; i < 32; i++) acc[i] = 0ull;
        MMA_BODY(ws, xs, acc, tx, ty)

        #pragma unroll
        for (int pr = 0; pr < 8; pr++) {
            int row0 = t * 128 + ty * 16 + 2 * pr;
            float c0[4], c1[4];
            upk(acc[pr],      c0[0], c1[0]);
            upk(acc[8 + pr],  c0[1], c1[1]);
            upk(acc[16 + pr], c0[2], c1[2]);
            upk(acc[24 + pr], c0[3], c1[3]);
            if (row0 < NPTS) {
                *(float4*)(hout + (size_t)row0 * 128 + tx * 4) =
                    make_float4(c0[0], c0[1], c0[2], c0[3]);
                if (row0 + 1 < NPTS)
                    *(float4*)(hout + (size_t)(row0 + 1) * 128 + tx * 4) =
                        make_float4(c1[0], c1[1], c1[2], c1[3]);
            }
        }
        __syncthreads();
    }
}

// ---------------- K4b (sequential fallback): fused W1 + Y + stats ----------------
#define SMEM_SEQ ((KP * 128 * 2 + 256 + 128) * 4)
__global__ __launch_bounds__(256, 2) void k_ptmm_fused(
    const float* __restrict__ pts, const float* __restrict__ proj,
    const float* __restrict__ feat, const float* __restrict__ logi,
    const int* __restrict__ cidx, const void* __restrict__ fgm,
    const float* __restrict__ W, float* __restrict__ hout)
{
    extern __shared__ __align__(16) float smf[];
    float* ws = smf;
    float* xs = smf + KP * 128;
    float* red = smf + KP * 256;
    int* sidx_s = (int*)(smf + KP * 256 + 256);

    const int tid = threadIdx.x;
    const int tx = tid & 31, ty = tid >> 5;
    const int r = tid & 127, half = tid >> 7;
    const int fl = g_flags;

    for (int i = tid; i < KP * 128; i += 256) {
        int k = i >> 7, n = i & 127;
        ws[i] = (k < 91) ? W[n * DIN + k] : 0.f;
    }
    float s_sum[4], s_sq[4];
    #pragma unroll
    for (int j = 0; j < 4; j++) { s_sum[j] = 0.f; s_sq[j] = 0.f; }
    __syncthreads();

    for (int t = blockIdx.x; t < NT_B; t += GRID) {
        const int p = t * 128 + r;
        const bool ok = p < NPTS;
        if (half == 0) sidx_s[r] = ok ? (cidx[p] * 2 + fg_of(fgm, p, fl)) : 0;
        gather_own(xs + r, pts, proj, feat, logi, p, ok, half);
        __syncthreads();

        unsigned long long acc[32];
        #pragma unroll
        for (int i = 0; i < 32; i++) acc[i] = 0ull;
        MMA_BODY(ws, xs, acc, tx, ty)

        #pragma unroll
        for (int pr = 0; pr < 8; pr++) {
            int rl = ty * 16 + 2 * pr;
            int row0 = t * 128 + rl;
            int s0 = sidx_s[rl], s1 = sidx_s[rl + 1];
            float4 y0 = *(const float4*)(g_Y + (size_t)s0 * 128 + tx * 4);
            float4 y1 = *(const float4*)(g_Y + (size_t)s1 * 128 + tx * 4);
            float c0[4], c1[4];
            upk(acc[pr],      c0[0], c1[0]);
            upk(acc[8 + pr],  c0[1], c1[1]);
            upk(acc[16 + pr], c0[2], c1[2]);
            upk(acc[24 + pr], c0[3], c1[3]);
            c0[0] += y0.x; c0[1] += y0.y; c0[2] += y0.z; c0[3] += y0.w;
            c1[0] += y1.x; c1[1] += y1.y; c1[2] += y1.z; c1[3] += y1.w;
            if (row0 < NPTS) {
                #pragma unroll
                for (int j = 0; j < 4; j++) { s_sum[j] += c0[j]; s_sq[j] += c0[j] * c0[j]; }
                *(float4*)(hout + (size_t)row0 * 128 + tx * 4) =
                    make_float4(c0[0], c0[1], c0[2], c0[3]);
                if (row0 + 1 < NPTS) {
                    #pragma unroll
                    for (int j = 0; j < 4; j++) { s_sum[j] += c1[j]; s_sq[j] += c1[j] * c1[j]; }
                    *(float4*)(hout + (size_t)(row0 + 1) * 128 + tx * 4) =
                        make_float4(c1[0], c1[1], c1[2], c1[3]);
                }
            }
        }
        __syncthreads();
    }

    if (tid < 256) red[tid] = 0.f;
    __syncthreads();
    #pragma unroll
    for (int j = 0; j < 4; j++) {
        atomicAdd(&red[tx * 4 + j], s_sum[j]);
        atomicAdd(&red[128 + tx * 4 + j], s_sq[j]);
    }
    __syncthreads();
    if (tid < 128) {
        atomicAdd(&g_sum[tid], red[tid]);
        atomicAdd(&g_sumsq[tid], red[128 + tid]);
    }
}

// ---------------- K5 (fork): stats over h + Y[seg] (no write) ----------------
__global__ __launch_bounds__(256) void k_stats2(const int* __restrict__ cidx,
                                                const void* __restrict__ fgm,
                                                const float* __restrict__ h) {
    __shared__ float red[256];
    const int tid = threadIdx.x, lane = tid & 31;
    const int gw = (blockIdx.x * blockDim.x + tid) >> 5;
    const int nw = (gridDim.x * blockDim.x) >> 5;
    const int fl = g_flags;
    float s0 = 0, s1 = 0, s2 = 0, s3 = 0, q0 = 0, q1 = 0, q2 = 0, q3 = 0;
    for (int p = gw; p < NPTS; p += nw) {
        int s = 0;
        if (lane == 0) s = cidx[p] * 2 + fg_of(fgm, p, fl);
        s = __shfl_sync(0xffffffffu, s, 0);
        float4 hv = __ldcs((const float4*)(h + (size_t)p * 128 + lane * 4));
        float4 yv = *(const float4*)(g_Y + (size_t)s * 128 + lane * 4);
        float v0 = hv.x + yv.x, v1 = hv.y + yv.y, v2 = hv.z + yv.z, v3 = hv.w + yv.w;
        s0 += v0; s1 += v1; s2 += v2; s3 += v3;
        q0 += v0 * v0; q1 += v1 * v1; q2 += v2 * v2; q3 += v3 * v3;
    }
    if (tid < 256) red[tid] = 0.f;
    __syncthreads();
    atomicAdd(&red[lane * 4 + 0], s0); atomicAdd(&red[lane * 4 + 1], s1);
    atomicAdd(&red[lane * 4 + 2], s2); atomicAdd(&red[lane * 4 + 3], s3);
    atomicAdd(&red[128 + lane * 4 + 0], q0); atomicAdd(&red[128 + lane * 4 + 1], q1);
    atomicAdd(&red[128 + lane * 4 + 2], q2); atomicAdd(&red[128 + lane * 4 + 3], q3);
    __syncthreads();
    if (tid < 128) {
        atomicAdd(&g_sum[tid], red[tid]);
        atomicAdd(&g_sumsq[tid], red[128 + tid]);
    }
}

// ---------------- K6: BN coefficients ----------------
__global__ void k_bn(const float* __restrict__ gamma, const float* __restrict__ beta) {
    int c = threadIdx.x;
    float mu = g_sum[c] * (1.0f / NPTS);
    float var = g_sumsq[c] * (1.0f / NPTS) - mu * mu;
    float sc = gamma[c] * rsqrtf(var + 1e-5f);
    g_scale[c] = sc;
    g_shift[c] = beta[c] - mu * sc;
}

// ---------------- K7a (fork): h = leaky(bn(h + Y[seg])) ----------------
__global__ __launch_bounds__(256) void k_apply2(const int* __restrict__ cidx,
                                                const void* __restrict__ fgm,
                                                float* __restrict__ h) {
    const int tid = threadIdx.x, lane = tid & 31;
    const int gw = (blockIdx.x * blockDim.x + tid) >> 5;
    const int nw = (gridDim.x * blockDim.x) >> 5;
    const int fl = g_flags;
    const int c = lane * 4;
    const float sc0 = g_scale[c], sc1 = g_scale[c + 1], sc2 = g_scale[c + 2], sc3 = g_scale[c + 3];
    const float sh0 = g_shift[c], sh1 = g_shift[c + 1], sh2 = g_shift[c + 2], sh3 = g_shift[c + 3];
    for (int p = gw; p < NPTS; p += nw) {
        int s = 0;
        if (lane == 0) s = cidx[p] * 2 + fg_of(fgm, p, fl);
        s = __shfl_sync(0xffffffffu, s, 0);
        float4 hv = __ldcs((const float4*)(h + (size_t)p * 128 + c));
        float4 yv = *(const float4*)(g_Y + (size_t)s * 128 + c);
        float a0 = (hv.x + yv.x) * sc0 + sh0;
        float a1 = (hv.y + yv.y) * sc1 + sh1;
        float a2 = (hv.z + yv.z) * sc2 + sh2;
        float a3 = (hv.w + yv.w) * sc3 + sh3;
        float4 o;
        o.x = a0 >= 0.f ? a0 : 0.1f * a0;
        o.y = a1 >= 0.f ? a1 : 0.1f * a1;
        o.z = a2 >= 0.f ? a2 : 0.1f * a2;
        o.w = a3 >= 0.f ? a3 : 0.1f * a3;
        __stcs((float4*)(h + (size_t)p * 128 + c), o);
    }
}

// ---------------- K7b (sequential): in-place normalize + LeakyReLU ----------------
__global__ __launch_bounds__(256) void k_apply(float* __restrict__ out) {
    int64_t i0 = (int64_t)blockIdx.x * blockDim.x + threadIdx.x;
    int64_t st = (int64_t)gridDim.x * blockDim.x;
    float4* o4 = (float4*)out;
    for (int64_t i = i0; i < (int64_t)NPTS * 32; i += st) {
        float4 v = o4[i];
        int c = (int)(i & 31) * 4;
        float a0 = v.x * g_scale[c]     + g_shift[c];
        float a1 = v.y * g_scale[c + 1] + g_shift[c + 1];
        float a2 = v.z * g_scale[c + 2] + g_shift[c + 2];
        float a3 = v.w * g_scale[c + 3] + g_shift[c + 3];
        v.x = a0 >= 0.f ? a0 : 0.1f * a0;
        v.y = a1 >= 0.f ? a1 : 0.1f * a1;
        v.z = a2 >= 0.f ? a2 : 0.1f * a2;
        v.w = a3 >= 0.f ? a3 : 0.1f * a3;
        o4[i] = v;
    }
}

extern "C" void kernel_launch(void* const* d_in, const int* in_sizes, int n_in,
                              void* d_out, int out_size) {
    const float* pts  = (const float*)d_in[0];
    const float* proj = (const float*)d_in[1];
    const float* feat = (const float*)d_in[2];
    const float* logi = (const float*)d_in[3];
    const int*   cidx = (const int*)d_in[4];
    const void*  fgm  = d_in[5];
    const float* W    = (const float*)d_in[6];
    const float* b    = (const float*)d_in[7];
    const float* gamma= (const float*)d_in[8];
    const float* beta = (const float*)d_in[9];
    float* out = (float*)d_out;

    static cudaStream_t side = nullptr;
    static cudaEvent_t ev0 = nullptr, ev1 = nullptr;
    static int inited = 0;
    if (!inited) {
        inited = 1;
        cudaFuncSetAttribute(k_segmm, cudaFuncAttributeMaxDynamicSharedMemorySize, SMEM_A);
        cudaFuncSetAttribute(k_ptmm_w1, cudaFuncAttributeMaxDynamicSharedMemorySize, SMEM_W1);
        cudaFuncSetAttribute(k_ptmm_fused, cudaFuncAttributeMaxDynamicSharedMemorySize, SMEM_SEQ);
        if (cudaStreamCreateWithFlags(&side, cudaStreamNonBlocking) != cudaSuccess) side = nullptr;
        if (side && cudaEventCreateWithFlags(&ev0, cudaEventDisableTiming) != cudaSuccess) side = nullptr;
        if (side && cudaEventCreateWithFlags(&ev1, cudaEventDisableTiming) != cudaSuccess) side = nullptr;
    }

    cudaStreamCaptureStatus st = cudaStreamCaptureStatusNone;
    cudaStreamIsCapturing((cudaStream_t)0, &st);

    if (st == cudaStreamCaptureStatusActive && side) {
        // forked graph: side = segment pipeline, main = W1 GEMM
        cudaEventRecord(ev0, (cudaStream_t)0);
        cudaStreamWaitEvent(side, ev0, 0);
        k_zero<<<GRID, 256, 0, side>>>();
        k_detect<<<64, 256, 0, side>>>((const unsigned int*)fgm);
        k_scatter<<<GRID, 256, 0, side>>>(pts, proj, feat, logi, cidx, fgm);
        k_segmm<<<GRID, 256, SMEM_A, side>>>(W, b);
        cudaEventRecord(ev1, side);
        k_ptmm_w1<<<GRID, 256, SMEM_W1>>>(pts, proj, feat, logi, W, out);
        cudaStreamWaitEvent((cudaStream_t)0, ev1, 0);
        k_stats2<<<2048, 256>>>(cidx, fgm, out);
        k_bn<<<1, 128>>>(gamma, beta);
        k_apply2<<<2048, 256>>>(cidx, fgm, out);
    } else {
        // sequential fallback (proven path)
        k_zero<<<2048, 256>>>();
        k_detect<<<64, 256>>>((const unsigned int*)fgm);
        k_scatter<<<2048, 256>>>(pts, proj, feat, logi, cidx, fgm);
        k_segmm<<<GRID, 256, SMEM_A>>>(W, b);
        k_ptmm_fused<<<GRID, 256, SMEM_SEQ>>>(pts, proj, feat, logi, cidx, fgm, W, out);
        k_bn<<<1, 128>>>(gamma, beta);
        k_apply<<<2048, 256>>>(out);
    }
}

// round 11
// speedup vs baseline: 1.0773x; 1.0773x over previous
#include <cuda_runtime.h>
#include <cstdint>

#define NPTS 500000
#define NSEG 80000
#define SEGW 92
#define DIN 182
#define NT_B 3907
#define NT_A 625
#define GRID 296
#define KP 92

__device__ __align__(16) float g_seg[NSEG * SEGW];
__device__ __align__(16) float g_Y[(size_t)NSEG * 128];
__device__ float g_sum[128], g_sumsq[128], g_scale[128], g_shift[128];
__device__ int g_flags;
__device__ int g_cnt[NSEG];
__device__ int g_base[NSEG];
__device__ int g_cur[NSEG];
__device__ int g_pidx[NPTS];

// ---- f32x2 packed helpers ----
__device__ __forceinline__ unsigned long long pk2(float a) {
    unsigned long long r; asm("mov.b64 %0,{%1,%1};" : "=l"(r) : "f"(a)); return r;
}
__device__ __forceinline__ void upk(unsigned long long v, float& a, float& b) {
    asm("mov.b64 {%0,%1},%2;" : "=f"(a), "=f"(b) : "l"(v));
}
__device__ __forceinline__ void fma2(unsigned long long& d, unsigned long long a, unsigned long long b) {
    asm("fma.rn.f32x2 %0,%1,%2,%0;" : "+l"(d) : "l"(a), "l"(b));
}
__device__ __forceinline__ int fg_of(const void* m, int p, int fl) {
    if (fl & 2) return ((const float*)m)[p] != 0.0f;
    if (fl & 1) return ((const unsigned char*)m)[p] != 0;
    return ((const int*)m)[p] != 0;
}

// ---------------- K0: zero small scratch (histogram + stats) ----------------
__global__ __launch_bounds__(256) void k_zero() {
    int i = blockIdx.x * blockDim.x + threadIdx.x;
    int st = gridDim.x * blockDim.x;
    for (int j = i; j < NSEG; j += st) g_cnt[j] = 0;
    if (i < 128) { g_sum[i] = 0.f; g_sumsq[i] = 0.f; }
    if (i == 0) g_flags = 0;
}

// ---------------- K1: detect fg_mask dtype ----------------
__global__ __launch_bounds__(256) void k_detect(const unsigned int* __restrict__ w) {
    int f = 0;
    for (int i = blockIdx.x * blockDim.x + threadIdx.x; i < 125000; i += gridDim.x * blockDim.x) {
        unsigned int x = w[i];
        if (x == 0x3f800000u) f |= 2;
        else if (x > 1u) f |= 1;
    }
    if (f) atomicOr(&g_flags, f);
}

// ---------------- K2a: histogram of segment sizes ----------------
__global__ __launch_bounds__(256) void k_hist(const int* __restrict__ cidx,
                                              const void* __restrict__ fgm) {
    const int fl = g_flags;
    for (int p = blockIdx.x * blockDim.x + threadIdx.x; p < NPTS; p += gridDim.x * blockDim.x)
        atomicAdd(&g_cnt[cidx[p] * 2 + fg_of(fgm, p, fl)], 1);
}

// ---------------- K2b: exclusive prefix scan (single block) ----------------
__global__ __launch_bounds__(1024) void k_scan() {
    __shared__ int part[1024];
    const int t = threadIdx.x;
    const int c0 = t * 79;                 // 1024*79 = 80896 >= NSEG
    int local = 0;
    #pragma unroll 1
    for (int j = 0; j < 79; j++) {
        int idx = c0 + j;
        if (idx < NSEG) local += g_cnt[idx];
    }
    part[t] = local;
    __syncthreads();
    for (int off = 1; off < 1024; off <<= 1) {
        int u = (t >= off) ? part[t - off] : 0;
        __syncthreads();
        part[t] += u;
        __syncthreads();
    }
    int run = part[t] - local;             // exclusive base for this chunk
    #pragma unroll 1
    for (int j = 0; j < 79; j++) {
        int idx = c0 + j;
        if (idx < NSEG) {
            int c = g_cnt[idx];
            g_base[idx] = run;
            g_cur[idx] = run;
            run += c;
        }
    }
}

// ---------------- K2c: reorder point ids by segment ----------------
__global__ __launch_bounds__(256) void k_reorder(const int* __restrict__ cidx,
                                                 const void* __restrict__ fgm) {
    const int fl = g_flags;
    for (int p = blockIdx.x * blockDim.x + threadIdx.x; p < NPTS; p += gridDim.x * blockDim.x) {
        int s = cidx[p] * 2 + fg_of(fgm, p, fl);
        int pos = atomicAdd(&g_cur[s], 1);
        g_pidx[pos] = p;
    }
}

// ---------------- K2d: gather-sum per segment (no fp atomics) ----------------
__device__ __forceinline__ float4 ldpt(const float* pts, const float* proj,
                                       const float* feat, const float* logi,
                                       int p, int lane) {
    if (lane < 16)  return *(const float4*)(feat + (size_t)p * 64 + lane * 4);
    if (lane < 21)  return *(const float4*)(logi + (size_t)p * 20 + (lane - 16) * 4);
    if (lane == 21) return *(const float4*)(pts + (size_t)p * 4);
    const float* pr = proj + (size_t)p * 3;
    return make_float4(pr[0], pr[1], pr[2], 0.f);
}

__global__ __launch_bounds__(256) void k_segsum(const float* __restrict__ pts,
                                                const float* __restrict__ proj,
                                                const float* __restrict__ feat,
                                                const float* __restrict__ logi) {
    const int lane = threadIdx.x & 31;
    const int gw = (blockIdx.x * blockDim.x + threadIdx.x) >> 5;
    const int nw = (gridDim.x * blockDim.x) >> 5;
    for (int s = gw; s < NSEG; s += nw) {
        const int n = g_cnt[s];
        const int base = g_base[s];
        float4 acc = make_float4(0.f, 0.f, 0.f, 0.f);
        if (lane < 23) {
            int i = 0;
            for (; i + 2 <= n; i += 2) {
                int p0 = g_pidx[base + i];
                int p1 = g_pidx[base + i + 1];
                float4 v0 = ldpt(pts, proj, feat, logi, p0, lane);
                float4 v1 = ldpt(pts, proj, feat, logi, p1, lane);
                acc.x += v0.x + v1.x; acc.y += v0.y + v1.y;
                acc.z += v0.z + v1.z; acc.w += v0.w + v1.w;
            }
            if (i < n) {
                float4 v = ldpt(pts, proj, feat, logi, g_pidx[base + i], lane);
                acc.x += v.x; acc.y += v.y; acc.z += v.z; acc.w += v.w;
            }
            if (lane == 22) acc.w = (float)n;      // count in col 91
            *(float4*)(g_seg + (size_t)s * SEGW + lane * 4) = acc;
        }
    }
}

// ======== FFMA2 inner block: 16m x 4n per thread, K=KP ========
#define MMA_BODY(ws, xs, acc, tx, ty)                                        \
    _Pragma("unroll 4")                                                       \
    for (int k = 0; k < KP; k++) {                                            \
        const float* xr = (xs) + k * 128 + (ty) * 16;                         \
        ulonglong2 a0 = *(const ulonglong2*)xr;                               \
        ulonglong2 a1 = *(const ulonglong2*)(xr + 4);                         \
        ulonglong2 a2 = *(const ulonglong2*)(xr + 8);                         \
        ulonglong2 a3 = *(const ulonglong2*)(xr + 12);                        \
        float4 b = *(const float4*)((ws) + k * 128 + (tx) * 4);               \
        unsigned long long b0 = pk2(b.x), b1 = pk2(b.y),                      \
                           b2 = pk2(b.z), b3 = pk2(b.w);                      \
        fma2(acc[0], a0.x, b0);  fma2(acc[1], a0.y, b0);                      \
        fma2(acc[2], a1.x, b0);  fma2(acc[3], a1.y, b0);                      \
        fma2(acc[4], a2.x, b0);  fma2(acc[5], a2.y, b0);                      \
        fma2(acc[6], a3.x, b0);  fma2(acc[7], a3.y, b0);                      \
        fma2(acc[8], a0.x, b1);  fma2(acc[9], a0.y, b1);                      \
        fma2(acc[10], a1.x, b1); fma2(acc[11], a1.y, b1);                     \
        fma2(acc[12], a2.x, b1); fma2(acc[13], a2.y, b1);                     \
        fma2(acc[14], a3.x, b1); fma2(acc[15], a3.y, b1);                     \
        fma2(acc[16], a0.x, b2); fma2(acc[17], a0.y, b2);                     \
        fma2(acc[18], a1.x, b2); fma2(acc[19], a1.y, b2);                     \
        fma2(acc[20], a2.x, b2); fma2(acc[21], a2.y, b2);                     \
        fma2(acc[22], a3.x, b2); fma2(acc[23], a3.y, b2);                     \
        fma2(acc[24], a0.x, b3); fma2(acc[25], a0.y, b3);                     \
        fma2(acc[26], a1.x, b3); fma2(acc[27], a1.y, b3);                     \
        fma2(acc[28], a2.x, b3); fma2(acc[29], a2.y, b3);                     \
        fma2(acc[30], a3.x, b3); fma2(acc[31], a3.y, b3);                     \
    }

// own-point gather into xs[k][m], K=92 layout
__device__ __forceinline__ void gather_own(
    float* xc, const float* pts, const float* proj, const float* feat,
    const float* logi, int p, bool ok, int half) {
    if (half == 0) {
        if (ok) {
            #pragma unroll
            for (int q = 0; q < 12; q++) {
                float4 f = *(const float4*)(feat + (size_t)p * 64 + 4 * q);
                xc[(4 * q + 0) * 128] = f.x; xc[(4 * q + 1) * 128] = f.y;
                xc[(4 * q + 2) * 128] = f.z; xc[(4 * q + 3) * 128] = f.w;
            }
        } else {
            #pragma unroll
            for (int k = 0; k < 48; k++) xc[k * 128] = 0.f;
        }
    } else {
        if (ok) {
            #pragma unroll
            for (int q = 0; q < 4; q++) {
                float4 f = *(const float4*)(feat + (size_t)p * 64 + 48 + 4 * q);
                xc[(48 + 4 * q) * 128] = f.x; xc[(49 + 4 * q) * 128] = f.y;
                xc[(50 + 4 * q) * 128] = f.z; xc[(51 + 4 * q) * 128] = f.w;
            }
            #pragma unroll
            for (int q = 0; q < 5; q++) {
                float4 f = *(const float4*)(logi + (size_t)p * 20 + 4 * q);
                xc[(64 + 4 * q) * 128] = f.x; xc[(65 + 4 * q) * 128] = f.y;
                xc[(66 + 4 * q) * 128] = f.z; xc[(67 + 4 * q) * 128] = f.w;
            }
            float4 f = *(const float4*)(pts + (size_t)p * 4);
            xc[84 * 128] = f.x; xc[85 * 128] = f.y; xc[86 * 128] = f.z; xc[87 * 128] = f.w;
            const float* pr = proj + (size_t)p * 3;
            xc[88 * 128] = pr[0]; xc[89 * 128] = pr[1]; xc[90 * 128] = pr[2];
        } else {
            #pragma unroll
            for (int k = 48; k < 91; k++) xc[k * 128] = 0.f;
        }
        xc[91 * 128] = 0.f;
    }
}

// ---------------- K3: pass A — Y[s] = W2*mean[s] + bias ----------------
#define SMEM_A ((KP * 128 * 2 + 128) * 4)
__global__ __launch_bounds__(256, 2) void k_segmm(const float* __restrict__ W,
                                                  const float* __restrict__ bias) {
    extern __shared__ __align__(16) float smf[];
    float* ws = smf;
    float* xs = smf + KP * 128;
    float* bias_s = smf + KP * 256;

    const int tid = threadIdx.x;
    const int tx = tid & 31, ty = tid >> 5;
    const int r = tid & 127, half = tid >> 7;

    for (int i = tid; i < KP * 128; i += 256) {
        int k = i >> 7, n = i & 127;
        ws[i] = (k < 91) ? W[n * DIN + 91 + k] : 0.f;
    }
    if (tid < 128) bias_s[tid] = bias[tid];
    __syncthreads();

    for (int t = blockIdx.x; t < NT_A; t += GRID) {
        const int s = t * 128 + r;
        const float* row = g_seg + (size_t)s * SEGW;
        float cnt = row[91];
        float inv = (cnt > 0.f) ? (1.0f / cnt) : 0.f;
        float* xc = xs + r;
        if (half == 0) {
            #pragma unroll
            for (int q = 0; q < 12; q++) {
                float4 f = *(const float4*)(row + 4 * q);
                xc[(4 * q + 0) * 128] = f.x * inv; xc[(4 * q + 1) * 128] = f.y * inv;
                xc[(4 * q + 2) * 128] = f.z * inv; xc[(4 * q + 3) * 128] = f.w * inv;
            }
        } else {
            #pragma unroll
            for (int q = 0; q < 10; q++) {
                float4 f = *(const float4*)(row + 48 + 4 * q);
                xc[(48 + 4 * q) * 128] = f.x * inv; xc[(49 + 4 * q) * 128] = f.y * inv;
                xc[(50 + 4 * q) * 128] = f.z * inv; xc[(51 + 4 * q) * 128] = f.w * inv;
            }
            xc[88 * 128] = row[88] * inv;
            xc[89 * 128] = row[89] * inv;
            xc[90 * 128] = row[90] * inv;
            xc[91 * 128] = 0.f;
        }
        __syncthreads();

        unsigned long long acc[32];
        #pragma unroll
        for (int i = 0; i < 32; i++) acc[i] = 0ull;
        MMA_BODY(ws, xs, acc, tx, ty)

        const float bj0 = bias_s[tx * 4], bj1 = bias_s[tx * 4 + 1];
        const float bj2 = bias_s[tx * 4 + 2], bj3 = bias_s[tx * 4 + 3];
        #pragma unroll
        for (int pr = 0; pr < 8; pr++) {
            int s0 = t * 128 + ty * 16 + 2 * pr;
            float c0[4], c1[4];
            upk(acc[pr],      c0[0], c1[0]);
            upk(acc[8 + pr],  c0[1], c1[1]);
            upk(acc[16 + pr], c0[2], c1[2]);
            upk(acc[24 + pr], c0[3], c1[3]);
            *(float4*)(g_Y + (size_t)s0 * 128 + tx * 4) =
                make_float4(c0[0] + bj0, c0[1] + bj1, c0[2] + bj2, c0[3] + bj3);
            *(float4*)(g_Y + (size_t)(s0 + 1) * 128 + tx * 4) =
                make_float4(c1[0] + bj0, c1[1] + bj1, c1[2] + bj2, c1[3] + bj3);
        }
        __syncthreads();
    }
}

// ---------------- K4: pass B — h = W1*own + Y[seg], + stats ----------------
#define SMEM_SEQ ((KP * 128 * 2 + 256 + 128) * 4)
__global__ __launch_bounds__(256, 2) void k_ptmm_fused(
    const float* __restrict__ pts, const float* __restrict__ proj,
    const float* __restrict__ feat, const float* __restrict__ logi,
    const int* __restrict__ cidx, const void* __restrict__ fgm,
    const float* __restrict__ W, float* __restrict__ hout)
{
    extern __shared__ __align__(16) float smf[];
    float* ws = smf;
    float* xs = smf + KP * 128;
    float* red = smf + KP * 256;
    int* sidx_s = (int*)(smf + KP * 256 + 256);

    const int tid = threadIdx.x;
    const int tx = tid & 31, ty = tid >> 5;
    const int r = tid & 127, half = tid >> 7;
    const int fl = g_flags;

    for (int i = tid; i < KP * 128; i += 256) {
        int k = i >> 7, n = i & 127;
        ws[i] = (k < 91) ? W[n * DIN + k] : 0.f;
    }
    float s_sum[4], s_sq[4];
    #pragma unroll
    for (int j = 0; j < 4; j++) { s_sum[j] = 0.f; s_sq[j] = 0.f; }
    __syncthreads();

    for (int t = blockIdx.x; t < NT_B; t += GRID) {
        const int p = t * 128 + r;
        const bool ok = p < NPTS;
        if (half == 0) sidx_s[r] = ok ? (cidx[p] * 2 + fg_of(fgm, p, fl)) : 0;
        gather_own(xs + r, pts, proj, feat, logi, p, ok, half);
        __syncthreads();

        unsigned long long acc[32];
        #pragma unroll
        for (int i = 0; i < 32; i++) acc[i] = 0ull;
        MMA_BODY(ws, xs, acc, tx, ty)

        #pragma unroll
        for (int pr = 0; pr < 8; pr++) {
            int rl = ty * 16 + 2 * pr;
            int row0 = t * 128 + rl;
            int s0 = sidx_s[rl], s1 = sidx_s[rl + 1];
            float4 y0 = *(const float4*)(g_Y + (size_t)s0 * 128 + tx * 4);
            float4 y1 = *(const float4*)(g_Y + (size_t)s1 * 128 + tx * 4);
            float c0[4], c1[4];
            upk(acc[pr],      c0[0], c1[0]);
            upk(acc[8 + pr],  c0[1], c1[1]);
            upk(acc[16 + pr], c0[2], c1[2]);
            upk(acc[24 + pr], c0[3], c1[3]);
            c0[0] += y0.x; c0[1] += y0.y; c0[2] += y0.z; c0[3] += y0.w;
            c1[0] += y1.x; c1[1] += y1.y; c1[2] += y1.z; c1[3] += y1.w;
            if (row0 < NPTS) {
                #pragma unroll
                for (int j = 0; j < 4; j++) { s_sum[j] += c0[j]; s_sq[j] += c0[j] * c0[j]; }
                *(float4*)(hout + (size_t)row0 * 128 + tx * 4) =
                    make_float4(c0[0], c0[1], c0[2], c0[3]);
                if (row0 + 1 < NPTS) {
                    #pragma unroll
                    for (int j = 0; j < 4; j++) { s_sum[j] += c1[j]; s_sq[j] += c1[j] * c1[j]; }
                    *(float4*)(hout + (size_t)(row0 + 1) * 128 + tx * 4) =
                        make_float4(c1[0], c1[1], c1[2], c1[3]);
                }
            }
        }
        __syncthreads();
    }

    if (tid < 256) red[tid] = 0.f;
    __syncthreads();
    #pragma unroll
    for (int j = 0; j < 4; j++) {
        atomicAdd(&red[tx * 4 + j], s_sum[j]);
        atomicAdd(&red[128 + tx * 4 + j], s_sq[j]);
    }
    __syncthreads();
    if (tid < 128) {
        atomicAdd(&g_sum[tid], red[tid]);
        atomicAdd(&g_sumsq[tid], red[128 + tid]);
    }
}

// ---------------- K5: BN coefficients ----------------
__global__ void k_bn(const float* __restrict__ gamma, const float* __restrict__ beta) {
    int c = threadIdx.x;
    float mu = g_sum[c] * (1.0f / NPTS);
    float var = g_sumsq[c] * (1.0f / NPTS) - mu * mu;
    float sc = gamma[c] * rsqrtf(var + 1e-5f);
    g_scale[c] = sc;
    g_shift[c] = beta[c] - mu * sc;
}

// ---------------- K6: normalize + LeakyReLU ----------------
__global__ __launch_bounds__(256) void k_apply(float* __restrict__ out) {
    int64_t i0 = (int64_t)blockIdx.x * blockDim.x + threadIdx.x;
    int64_t st = (int64_t)gridDim.x * blockDim.x;
    float4* o4 = (float4*)out;
    for (int64_t i = i0; i < (int64_t)NPTS * 32; i += st) {
        float4 v = o4[i];
        int c = (int)(i & 31) * 4;
        float a0 = v.x * g_scale[c]     + g_shift[c];
        float a1 = v.y * g_scale[c + 1] + g_shift[c + 1];
        float a2 = v.z * g_scale[c + 2] + g_shift[c + 2];
        float a3 = v.w * g_scale[c + 3] + g_shift[c + 3];
        v.x = a0 >= 0.f ? a0 : 0.1f * a0;
        v.y = a1 >= 0.f ? a1 : 0.1f * a1;
        v.z = a2 >= 0.f ? a2 : 0.1f * a2;
        v.w = a3 >= 0.f ? a3 : 0.1f * a3;
        o4[i] = v;
    }
}

extern "C" void kernel_launch(void* const* d_in, const int* in_sizes, int n_in,
                              void* d_out, int out_size) {
    const float* pts  = (const float*)d_in[0];
    const float* proj = (const float*)d_in[1];
    const float* feat = (const float*)d_in[2];
    const float* logi = (const float*)d_in[3];
    const int*   cidx = (const int*)d_in[4];
    const void*  fgm  = d_in[5];
    const float* W    = (const float*)d_in[6];
    const float* b    = (const float*)d_in[7];
    const float* gamma= (const float*)d_in[8];
    const float* beta = (const float*)d_in[9];
    float* out = (float*)d_out;

    cudaFuncSetAttribute(k_segmm, cudaFuncAttributeMaxDynamicSharedMemorySize, SMEM_A);
    cudaFuncSetAttribute(k_ptmm_fused, cudaFuncAttributeMaxDynamicSharedMemorySize, SMEM_SEQ);

    k_zero<<<320, 256>>>();
    k_detect<<<64, 256>>>((const unsigned int*)fgm);
    k_hist<<<512, 256>>>(cidx, fgm);
    k_scan<<<1, 1024>>>();
    k_reorder<<<512, 256>>>(cidx, fgm);
    k_segsum<<<2500, 256>>>(pts, proj, feat, logi);
    k_segmm<<<GRID, 256, SMEM_A>>>(W, b);
    k_ptmm_fused<<<GRID, 256, SMEM_SEQ>>>(pts, proj, feat, logi, cidx, fgm, W, out);
    k_bn<<<1, 128>>>(gamma, beta);
    k_apply<<<2048, 256>>>(out);
}

// round 12
// speedup vs baseline: 1.3209x; 1.2261x over previous
#include <cuda_runtime.h>
#include <cstdint>

#define NPTS 500000
#define NSEG 80000
#define SEGW 92
#define DIN 182
#define NT_B 3907
#define NT_A 625
#define GRID 296
#define KP 92

__device__ __align__(16) float g_seg[NSEG * SEGW];
__device__ __align__(16) float g_Y[(size_t)NSEG * 128];
__device__ float g_sum[128], g_sumsq[128], g_scale[128], g_shift[128];
__device__ int g_flags;
__device__ int g_cnt[NSEG];
__device__ int g_base[NSEG];
__device__ int g_cur[NSEG];
__device__ int g_pidx[NPTS];
__device__ int g_blksum[640];
__device__ int g_blkoff[640];

// ---- f32x2 packed helpers ----
__device__ __forceinline__ unsigned long long pk2(float a) {
    unsigned long long r; asm("mov.b64 %0,{%1,%1};" : "=l"(r) : "f"(a)); return r;
}
__device__ __forceinline__ void upk(unsigned long long v, float& a, float& b) {
    asm("mov.b64 {%0,%1},%2;" : "=f"(a), "=f"(b) : "l"(v));
}
__device__ __forceinline__ void fma2(unsigned long long& d, unsigned long long a, unsigned long long b) {
    asm("fma.rn.f32x2 %0,%1,%2,%0;" : "+l"(d) : "l"(a), "l"(b));
}
__device__ __forceinline__ int fg_of(const void* m, int p, int fl) {
    if (fl & 2) return ((const float*)m)[p] != 0.0f;
    if (fl & 1) return ((const unsigned char*)m)[p] != 0;
    return ((const int*)m)[p] != 0;
}

// ---------------- K0: zero small scratch ----------------
__global__ __launch_bounds__(256) void k_zero() {
    int i = blockIdx.x * blockDim.x + threadIdx.x;
    int st = gridDim.x * blockDim.x;
    for (int j = i; j < NSEG; j += st) g_cnt[j] = 0;
    if (i < 128) { g_sum[i] = 0.f; g_sumsq[i] = 0.f; }
    if (i == 0) g_flags = 0;
}

// ---------------- K1: detect fg_mask dtype ----------------
__global__ __launch_bounds__(256) void k_detect(const unsigned int* __restrict__ w) {
    int f = 0;
    for (int i = blockIdx.x * blockDim.x + threadIdx.x; i < 125000; i += gridDim.x * blockDim.x) {
        unsigned int x = w[i];
        if (x == 0x3f800000u) f |= 2;
        else if (x > 1u) f |= 1;
    }
    if (f) atomicOr(&g_flags, f);
}

// ---------------- K2a: histogram of segment sizes ----------------
__global__ __launch_bounds__(256) void k_hist(const int* __restrict__ cidx,
                                              const void* __restrict__ fgm) {
    const int fl = g_flags;
    for (int p = blockIdx.x * blockDim.x + threadIdx.x; p < NPTS; p += gridDim.x * blockDim.x)
        atomicAdd(&g_cnt[cidx[p] * 2 + fg_of(fgm, p, fl)], 1);
}

// ---------------- K2b: three-phase parallel exclusive scan ----------------
// phase 1: per-block (128-wide) exclusive scan + block totals
__global__ __launch_bounds__(128) void k_scan1() {
    __shared__ int sh[128];
    const int t = threadIdx.x;
    const int i = blockIdx.x * 128 + t;
    int c = g_cnt[i];
    sh[t] = c;
    __syncthreads();
    int acc = c;
    #pragma unroll
    for (int off = 1; off < 128; off <<= 1) {
        int u = (t >= off) ? sh[t - off] : 0;
        __syncthreads();
        acc += u;
        sh[t] = acc;
        __syncthreads();
    }
    g_base[i] = acc - c;                  // exclusive within block
    if (t == 127) g_blksum[blockIdx.x] = acc;
}
// phase 2: scan the 625 block totals (single block)
__global__ __launch_bounds__(1024) void k_scan2() {
    __shared__ int sh[1024];
    const int t = threadIdx.x;
    int c = (t < NT_A) ? g_blksum[t] : 0;
    sh[t] = c;
    __syncthreads();
    int acc = c;
    #pragma unroll
    for (int off = 1; off < 1024; off <<= 1) {
        int u = (t >= off) ? sh[t - off] : 0;
        __syncthreads();
        acc += u;
        sh[t] = acc;
        __syncthreads();
    }
    if (t < NT_A) g_blkoff[t] = acc - c;  // exclusive block offset
}
// phase 3: add offsets, init cursors
__global__ __launch_bounds__(128) void k_scan3() {
    const int i = blockIdx.x * 128 + threadIdx.x;
    int v = g_base[i] + g_blkoff[blockIdx.x];
    g_base[i] = v;
    g_cur[i] = v;
}

// ---------------- K2c: reorder point ids by segment ----------------
__global__ __launch_bounds__(256) void k_reorder(const int* __restrict__ cidx,
                                                 const void* __restrict__ fgm) {
    const int fl = g_flags;
    for (int p = blockIdx.x * blockDim.x + threadIdx.x; p < NPTS; p += gridDim.x * blockDim.x) {
        int s = cidx[p] * 2 + fg_of(fgm, p, fl);
        int pos = atomicAdd(&g_cur[s], 1);
        g_pidx[pos] = p;
    }
}

// ---------------- K2d: gather-sum per segment (no fp atomics) ----------------
__device__ __forceinline__ float4 ldpt(const float* pts, const float* proj,
                                       const float* feat, const float* logi,
                                       int p, int lane) {
    if (lane < 16)  return *(const float4*)(feat + (size_t)p * 64 + lane * 4);
    if (lane < 21)  return *(const float4*)(logi + (size_t)p * 20 + (lane - 16) * 4);
    if (lane == 21) return *(const float4*)(pts + (size_t)p * 4);
    const float* pr = proj + (size_t)p * 3;
    return make_float4(pr[0], pr[1], pr[2], 0.f);
}

__global__ __launch_bounds__(256) void k_segsum(const float* __restrict__ pts,
                                                const float* __restrict__ proj,
                                                const float* __restrict__ feat,
                                                const float* __restrict__ logi) {
    const int lane = threadIdx.x & 31;
    const int gw = (blockIdx.x * blockDim.x + threadIdx.x) >> 5;
    const int nw = (gridDim.x * blockDim.x) >> 5;
    for (int s = gw; s < NSEG; s += nw) {
        const int n = g_cnt[s];
        const int base = g_base[s];
        float4 acc = make_float4(0.f, 0.f, 0.f, 0.f);
        if (lane < 23) {
            int i = 0;
            for (; i + 2 <= n; i += 2) {
                int p0 = g_pidx[base + i];
                int p1 = g_pidx[base + i + 1];
                float4 v0 = ldpt(pts, proj, feat, logi, p0, lane);
                float4 v1 = ldpt(pts, proj, feat, logi, p1, lane);
                acc.x += v0.x + v1.x; acc.y += v0.y + v1.y;
                acc.z += v0.z + v1.z; acc.w += v0.w + v1.w;
            }
            if (i < n) {
                float4 v = ldpt(pts, proj, feat, logi, g_pidx[base + i], lane);
                acc.x += v.x; acc.y += v.y; acc.z += v.z; acc.w += v.w;
            }
            if (lane == 22) acc.w = (float)n;      // count in col 91
            *(float4*)(g_seg + (size_t)s * SEGW + lane * 4) = acc;
        }
    }
}

// ======== FFMA2 inner block: 16m x 4n per thread, K=KP ========
#define MMA_BODY(ws, xs, acc, tx, ty)                                        \
    _Pragma("unroll 4")                                                       \
    for (int k = 0; k < KP; k++) {                                            \
        const float* xr = (xs) + k * 128 + (ty) * 16;                         \
        ulonglong2 a0 = *(const ulonglong2*)xr;                               \
        ulonglong2 a1 = *(const ulonglong2*)(xr + 4);                         \
        ulonglong2 a2 = *(const ulonglong2*)(xr + 8);                         \
        ulonglong2 a3 = *(const ulonglong2*)(xr + 12);                        \
        float4 b = *(const float4*)((ws) + k * 128 + (tx) * 4);               \
        unsigned long long b0 = pk2(b.x), b1 = pk2(b.y),                      \
                           b2 = pk2(b.z), b3 = pk2(b.w);                      \
        fma2(acc[0], a0.x, b0);  fma2(acc[1], a0.y, b0);                      \
        fma2(acc[2], a1.x, b0);  fma2(acc[3], a1.y, b0);                      \
        fma2(acc[4], a2.x, b0);  fma2(acc[5], a2.y, b0);                      \
        fma2(acc[6], a3.x, b0);  fma2(acc[7], a3.y, b0);                      \
        fma2(acc[8], a0.x, b1);  fma2(acc[9], a0.y, b1);                      \
        fma2(acc[10], a1.x, b1); fma2(acc[11], a1.y, b1);                     \
        fma2(acc[12], a2.x, b1); fma2(acc[13], a2.y, b1);                     \
        fma2(acc[14], a3.x, b1); fma2(acc[15], a3.y, b1);                     \
        fma2(acc[16], a0.x, b2); fma2(acc[17], a0.y, b2);                     \
        fma2(acc[18], a1.x, b2); fma2(acc[19], a1.y, b2);                     \
        fma2(acc[20], a2.x, b2); fma2(acc[21], a2.y, b2);                     \
        fma2(acc[22], a3.x, b2); fma2(acc[23], a3.y, b2);                     \
        fma2(acc[24], a0.x, b3); fma2(acc[25], a0.y, b3);                     \
        fma2(acc[26], a1.x, b3); fma2(acc[27], a1.y, b3);                     \
        fma2(acc[28], a2.x, b3); fma2(acc[29], a2.y, b3);                     \
        fma2(acc[30], a3.x, b3); fma2(acc[31], a3.y, b3);                     \
    }

// own-point gather into xs[k][m], K=92 layout
__device__ __forceinline__ void gather_own(
    float* xc, const float* pts, const float* proj, const float* feat,
    const float* logi, int p, bool ok, int half) {
    if (half == 0) {
        if (ok) {
            #pragma unroll
            for (int q = 0; q < 12; q++) {
                float4 f = *(const float4*)(feat + (size_t)p * 64 + 4 * q);
                xc[(4 * q + 0) * 128] = f.x; xc[(4 * q + 1) * 128] = f.y;
                xc[(4 * q + 2) * 128] = f.z; xc[(4 * q + 3) * 128] = f.w;
            }
        } else {
            #pragma unroll
            for (int k = 0; k < 48; k++) xc[k * 128] = 0.f;
        }
    } else {
        if (ok) {
            #pragma unroll
            for (int q = 0; q < 4; q++) {
                float4 f = *(const float4*)(feat + (size_t)p * 64 + 48 + 4 * q);
                xc[(48 + 4 * q) * 128] = f.x; xc[(49 + 4 * q) * 128] = f.y;
                xc[(50 + 4 * q) * 128] = f.z; xc[(51 + 4 * q) * 128] = f.w;
            }
            #pragma unroll
            for (int q = 0; q < 5; q++) {
                float4 f = *(const float4*)(logi + (size_t)p * 20 + 4 * q);
                xc[(64 + 4 * q) * 128] = f.x; xc[(65 + 4 * q) * 128] = f.y;
                xc[(66 + 4 * q) * 128] = f.z; xc[(67 + 4 * q) * 128] = f.w;
            }
            float4 f = *(const float4*)(pts + (size_t)p * 4);
            xc[84 * 128] = f.x; xc[85 * 128] = f.y; xc[86 * 128] = f.z; xc[87 * 128] = f.w;
            const float* pr = proj + (size_t)p * 3;
            xc[88 * 128] = pr[0]; xc[89 * 128] = pr[1]; xc[90 * 128] = pr[2];
        } else {
            #pragma unroll
            for (int k = 48; k < 91; k++) xc[k * 128] = 0.f;
        }
        xc[91 * 128] = 0.f;
    }
}

// ---------------- K3: pass A — Y[s] = W2*mean[s] + bias ----------------
#define SMEM_A ((KP * 128 * 2 + 128) * 4)
__global__ __launch_bounds__(256, 2) void k_segmm(const float* __restrict__ W,
                                                  const float* __restrict__ bias) {
    extern __shared__ __align__(16) float smf[];
    float* ws = smf;
    float* xs = smf + KP * 128;
    float* bias_s = smf + KP * 256;

    const int tid = threadIdx.x;
    const int tx = tid & 31, ty = tid >> 5;
    const int r = tid & 127, half = tid >> 7;

    for (int i = tid; i < KP * 128; i += 256) {
        int k = i >> 7, n = i & 127;
        ws[i] = (k < 91) ? W[n * DIN + 91 + k] : 0.f;
    }
    if (tid < 128) bias_s[tid] = bias[tid];
    __syncthreads();

    for (int t = blockIdx.x; t < NT_A; t += GRID) {
        const int s = t * 128 + r;
        const float* row = g_seg + (size_t)s * SEGW;
        float cnt = row[91];
        float inv = (cnt > 0.f) ? (1.0f / cnt) : 0.f;
        float* xc = xs + r;
        if (half == 0) {
            #pragma unroll
            for (int q = 0; q < 12; q++) {
                float4 f = *(const float4*)(row + 4 * q);
                xc[(4 * q + 0) * 128] = f.x * inv; xc[(4 * q + 1) * 128] = f.y * inv;
                xc[(4 * q + 2) * 128] = f.z * inv; xc[(4 * q + 3) * 128] = f.w * inv;
            }
        } else {
            #pragma unroll
            for (int q = 0; q < 10; q++) {
                float4 f = *(const float4*)(row + 48 + 4 * q);
                xc[(48 + 4 * q) * 128] = f.x * inv; xc[(49 + 4 * q) * 128] = f.y * inv;
                xc[(50 + 4 * q) * 128] = f.z * inv; xc[(51 + 4 * q) * 128] = f.w * inv;
            }
            xc[88 * 128] = row[88] * inv;
            xc[89 * 128] = row[89] * inv;
            xc[90 * 128] = row[90] * inv;
            xc[91 * 128] = 0.f;
        }
        __syncthreads();

        unsigned long long acc[32];
        #pragma unroll
        for (int i = 0; i < 32; i++) acc[i] = 0ull;
        MMA_BODY(ws, xs, acc, tx, ty)

        const float bj0 = bias_s[tx * 4], bj1 = bias_s[tx * 4 + 1];
        const float bj2 = bias_s[tx * 4 + 2], bj3 = bias_s[tx * 4 + 3];
        #pragma unroll
        for (int pr = 0; pr < 8; pr++) {
            int s0 = t * 128 + ty * 16 + 2 * pr;
            float c0[4], c1[4];
            upk(acc[pr],      c0[0], c1[0]);
            upk(acc[8 + pr],  c0[1], c1[1]);
            upk(acc[16 + pr], c0[2], c1[2]);
            upk(acc[24 + pr], c0[3], c1[3]);
            *(float4*)(g_Y + (size_t)s0 * 128 + tx * 4) =
                make_float4(c0[0] + bj0, c0[1] + bj1, c0[2] + bj2, c0[3] + bj3);
            *(float4*)(g_Y + (size_t)(s0 + 1) * 128 + tx * 4) =
                make_float4(c1[0] + bj0, c1[1] + bj1, c1[2] + bj2, c1[3] + bj3);
        }
        __syncthreads();
    }
}

// ---------------- K4: pass B — h = W1*own + Y[seg], + stats ----------------
#define SMEM_SEQ ((KP * 128 * 2 + 256 + 128) * 4)
__global__ __launch_bounds__(256, 2) void k_ptmm_fused(
    const float* __restrict__ pts, const float* __restrict__ proj,
    const float* __restrict__ feat, const float* __restrict__ logi,
    const int* __restrict__ cidx, const void* __restrict__ fgm,
    const float* __restrict__ W, float* __restrict__ hout)
{
    extern __shared__ __align__(16) float smf[];
    float* ws = smf;
    float* xs = smf + KP * 128;
    float* red = smf + KP * 256;
    int* sidx_s = (int*)(smf + KP * 256 + 256);

    const int tid = threadIdx.x;
    const int tx = tid & 31, ty = tid >> 5;
    const int r = tid & 127, half = tid >> 7;
    const int fl = g_flags;

    for (int i = tid; i < KP * 128; i += 256) {
        int k = i >> 7, n = i & 127;
        ws[i] = (k < 91) ? W[n * DIN + k] : 0.f;
    }
    float s_sum[4], s_sq[4];
    #pragma unroll
    for (int j = 0; j < 4; j++) { s_sum[j] = 0.f; s_sq[j] = 0.f; }
    __syncthreads();

    for (int t = blockIdx.x; t < NT_B; t += GRID) {
        const int p = t * 128 + r;
        const bool ok = p < NPTS;
        if (half == 0) sidx_s[r] = ok ? (cidx[p] * 2 + fg_of(fgm, p, fl)) : 0;
        gather_own(xs + r, pts, proj, feat, logi, p, ok, half);
        __syncthreads();

        unsigned long long acc[32];
        #pragma unroll
        for (int i = 0; i < 32; i++) acc[i] = 0ull;
        MMA_BODY(ws, xs, acc, tx, ty)

        #pragma unroll
        for (int pr = 0; pr < 8; pr++) {
            int rl = ty * 16 + 2 * pr;
            int row0 = t * 128 + rl;
            int s0 = sidx_s[rl], s1 = sidx_s[rl + 1];
            float4 y0 = *(const float4*)(g_Y + (size_t)s0 * 128 + tx * 4);
            float4 y1 = *(const float4*)(g_Y + (size_t)s1 * 128 + tx * 4);
            float c0[4], c1[4];
            upk(acc[pr],      c0[0], c1[0]);
            upk(acc[8 + pr],  c0[1], c1[1]);
            upk(acc[16 + pr], c0[2], c1[2]);
            upk(acc[24 + pr], c0[3], c1[3]);
            c0[0] += y0.x; c0[1] += y0.y; c0[2] += y0.z; c0[3] += y0.w;
            c1[0] += y1.x; c1[1] += y1.y; c1[2] += y1.z; c1[3] += y1.w;
            if (row0 < NPTS) {
                #pragma unroll
                for (int j = 0; j < 4; j++) { s_sum[j] += c0[j]; s_sq[j] += c0[j] * c0[j]; }
                *(float4*)(hout + (size_t)row0 * 128 + tx * 4) =
                    make_float4(c0[0], c0[1], c0[2], c0[3]);
                if (row0 + 1 < NPTS) {
                    #pragma unroll
                    for (int j = 0; j < 4; j++) { s_sum[j] += c1[j]; s_sq[j] += c1[j] * c1[j]; }
                    *(float4*)(hout + (size_t)(row0 + 1) * 128 + tx * 4) =
                        make_float4(c1[0], c1[1], c1[2], c1[3]);
                }
            }
        }
        __syncthreads();
    }

    if (tid < 256) red[tid] = 0.f;
    __syncthreads();
    #pragma unroll
    for (int j = 0; j < 4; j++) {
        atomicAdd(&red[tx * 4 + j], s_sum[j]);
        atomicAdd(&red[128 + tx * 4 + j], s_sq[j]);
    }
    __syncthreads();
    if (tid < 128) {
        atomicAdd(&g_sum[tid], red[tid]);
        atomicAdd(&g_sumsq[tid], red[128 + tid]);
    }
}

// ---------------- K5: BN coefficients ----------------
__global__ void k_bn(const float* __restrict__ gamma, const float* __restrict__ beta) {
    int c = threadIdx.x;
    float mu = g_sum[c] * (1.0f / NPTS);
    float var = g_sumsq[c] * (1.0f / NPTS) - mu * mu;
    float sc = gamma[c] * rsqrtf(var + 1e-5f);
    g_scale[c] = sc;
    g_shift[c] = beta[c] - mu * sc;
}

// ---------------- K6: normalize + LeakyReLU ----------------
__global__ __launch_bounds__(256) void k_apply(float* __restrict__ out) {
    int64_t i0 = (int64_t)blockIdx.x * blockDim.x + threadIdx.x;
    int64_t st = (int64_t)gridDim.x * blockDim.x;
    float4* o4 = (float4*)out;
    for (int64_t i = i0; i < (int64_t)NPTS * 32; i += st) {
        float4 v = o4[i];
        int c = (int)(i & 31) * 4;
        float a0 = v.x * g_scale[c]     + g_shift[c];
        float a1 = v.y * g_scale[c + 1] + g_shift[c + 1];
        float a2 = v.z * g_scale[c + 2] + g_shift[c + 2];
        float a3 = v.w * g_scale[c + 3] + g_shift[c + 3];
        v.x = a0 >= 0.f ? a0 : 0.1f * a0;
        v.y = a1 >= 0.f ? a1 : 0.1f * a1;
        v.z = a2 >= 0.f ? a2 : 0.1f * a2;
        v.w = a3 >= 0.f ? a3 : 0.1f * a3;
        o4[i] = v;
    }
}

extern "C" void kernel_launch(void* const* d_in, const int* in_sizes, int n_in,
                              void* d_out, int out_size) {
    const float* pts  = (const float*)d_in[0];
    const float* proj = (const float*)d_in[1];
    const float* feat = (const float*)d_in[2];
    const float* logi = (const float*)d_in[3];
    const int*   cidx = (const int*)d_in[4];
    const void*  fgm  = d_in[5];
    const float* W    = (const float*)d_in[6];
    const float* b    = (const float*)d_in[7];
    const float* gamma= (const float*)d_in[8];
    const float* beta = (const float*)d_in[9];
    float* out = (float*)d_out;

    cudaFuncSetAttribute(k_segmm, cudaFuncAttributeMaxDynamicSharedMemorySize, SMEM_A);
    cudaFuncSetAttribute(k_ptmm_fused, cudaFuncAttributeMaxDynamicSharedMemorySize, SMEM_SEQ);

    k_zero<<<320, 256>>>();
    k_detect<<<64, 256>>>((const unsigned int*)fgm);
    k_hist<<<512, 256>>>(cidx, fgm);
    k_scan1<<<NT_A, 128>>>();
    k_scan2<<<1, 1024>>>();
    k_scan3<<<NT_A, 128>>>();
    k_reorder<<<512, 256>>>(cidx, fgm);
    k_segsum<<<2500, 256>>>(pts, proj, feat, logi);
    k_segmm<<<GRID, 256, SMEM_A>>>(W, b);
    k_ptmm_fused<<<GRID, 256, SMEM_SEQ>>>(pts, proj, feat, logi, cidx, fgm, W, out);
    k_bn<<<1, 128>>>(gamma, beta);
    k_apply<<<2048, 256>>>(out);
}